// round 1
// baseline (speedup 1.0000x reference)
#include <cuda_runtime.h>
#include <math.h>

// Problem-fixed sizes (from reference): N=100000, E=1600000, D=128, EIG=32.
#define MAXN 100000
#define MAXE 1600000

// Scratch (device globals — no allocation allowed in kernel_launch).
__device__ float g_me[MAXN];        // per-node motif embedding value
__device__ int   g_cnt[MAXN];       // histogram, then scatter cursor
__device__ int   g_off[MAXN + 1];   // CSR row offsets
__device__ float g_acc[3];          // sum(ab), sum(a2), sum(b2)
__device__ float g_par[2];          // [0]=exp(lambda0), [1]=c = gamma*sim
__device__ int   g_col_s[MAXE];     // col sorted by row
__device__ float g_adj_s[MAXE];     // adj sorted by row
__device__ float g_s0[MAXE];        // per-edge score s0 in sorted order

// ---------------------------------------------------------------------------
// K0: zero counters/accumulators, compute me[n] = motif_emb_w[motif_ids[n]]
// ---------------------------------------------------------------------------
__global__ void k_init(const float* __restrict__ memb,
                       const int* __restrict__ mids, int n) {
    int i = blockIdx.x * blockDim.x + threadIdx.x;
    if (i == 0) { g_acc[0] = 0.f; g_acc[1] = 0.f; g_acc[2] = 0.f; }
    if (i < n) {
        g_me[i]  = memb[mids[i]];
        g_cnt[i] = 0;
    }
}

// ---------------------------------------------------------------------------
// K1: edge-level scalar reductions (for cosine sim) + row histogram
// ---------------------------------------------------------------------------
__global__ void k_edge1(const int* __restrict__ row,
                        const int* __restrict__ col, int e) {
    float pab = 0.f, pa2 = 0.f, pb2 = 0.f;
    for (int i = blockIdx.x * blockDim.x + threadIdx.x; i < e;
         i += gridDim.x * blockDim.x) {
        int r = row[i], c = col[i];
        atomicAdd(&g_cnt[r], 1);
        float a = g_me[r], b = g_me[c];
        pab = fmaf(a, b, pab);
        pa2 = fmaf(a, a, pa2);
        pb2 = fmaf(b, b, pb2);
    }
#pragma unroll
    for (int o = 16; o; o >>= 1) {
        pab += __shfl_down_sync(0xffffffffu, pab, o);
        pa2 += __shfl_down_sync(0xffffffffu, pa2, o);
        pb2 += __shfl_down_sync(0xffffffffu, pb2, o);
    }
    __shared__ float sb[3][8];
    int w = threadIdx.x >> 5, l = threadIdx.x & 31;
    if (!l) { sb[0][w] = pab; sb[1][w] = pa2; sb[2][w] = pb2; }
    __syncthreads();
    if (!threadIdx.x) {
        float t0 = 0.f, t1 = 0.f, t2 = 0.f;
        int nw = blockDim.x >> 5;
        for (int j = 0; j < nw; j++) { t0 += sb[0][j]; t1 += sb[1][j]; t2 += sb[2][j]; }
        atomicAdd(&g_acc[0], t0);
        atomicAdd(&g_acc[1], t1);
        atomicAdd(&g_acc[2], t2);
    }
}

// ---------------------------------------------------------------------------
// K2: exclusive scan of histogram -> CSR offsets + cursor; compute scalars
// ---------------------------------------------------------------------------
__global__ void k_scan(const float* __restrict__ lambda0,
                       const float* __restrict__ gamma, int n, int e) {
    __shared__ int ssum[1024];
    int t = threadIdx.x;
    int chunk = (n + 1023) / 1024;
    int b = t * chunk;
    int en = b + chunk; if (en > n) en = n;
    int s = 0;
    for (int i = b; i < en; i++) s += g_cnt[i];
    ssum[t] = s;
    __syncthreads();
    if (!t) {
        int run = 0;
        for (int i = 0; i < 1024; i++) { int v = ssum[i]; ssum[i] = run; run += v; }
        g_off[n] = e;
        float sab = g_acc[0], sa2 = g_acc[1], sb2 = g_acc[2];
        float na = fmaxf(sqrtf(sa2), 1e-8f);
        float nb = fmaxf(sqrtf(sb2), 1e-8f);
        g_par[0] = expf(lambda0[0]);
        g_par[1] = gamma[0] * (sab / (na * nb));
    }
    __syncthreads();
    int run = ssum[t];
    for (int i = b; i < en; i++) {
        int v = g_cnt[i];
        g_off[i] = run;
        g_cnt[i] = run;  // cursor for the scatter pass
        run += v;
    }
}

// ---------------------------------------------------------------------------
// K3: counting-sort scatter of (col, adj) into row-sorted order
// ---------------------------------------------------------------------------
__global__ void k_scatter(const int* __restrict__ row,
                          const int* __restrict__ col,
                          const float* __restrict__ adj, int e) {
    for (int i = blockIdx.x * blockDim.x + threadIdx.x; i < e;
         i += gridDim.x * blockDim.x) {
        int pos = atomicAdd(&g_cnt[row[i]], 1);
        g_col_s[pos] = col[i];
        g_adj_s[pos] = adj[i];
    }
}

// ---------------------------------------------------------------------------
// K4: fused per-row kernel: scores + dual softmax + weighted V aggregation.
// One warp per destination row. Lane l owns floats [4l, 4l+4) of the 128-dim
// vectors (one float4) and eig component l (EIG=32).
// ---------------------------------------------------------------------------
__global__ void __launch_bounds__(256)
k_main(const float4* __restrict__ q4, const float4* __restrict__ k4p,
       const float4* __restrict__ v4p, const float* __restrict__ eigs,
       float4* __restrict__ out4, int n) {
    int wid  = (blockIdx.x * blockDim.x + threadIdx.x) >> 5;
    int lane = threadIdx.x & 31;
    if (wid >= n) return;
    int r     = wid;
    int start = g_off[r];
    int end   = g_off[r + 1];
    if (start == end) {  // empty segment: reference segment_sum yields zeros
        out4[r * 32 + lane] = make_float4(0.f, 0.f, 0.f, 0.f);
        return;
    }
    float lambda = g_par[0];
    float c      = g_par[1];
    const float inv = 0.08838834764831845f;  // 1/sqrt(128)

    float4 q  = q4[r * 32 + lane];
    float  er = eigs[r * 32 + lane];

    // -------- pass 1: per-edge score s0, running maxima --------
    float m0 = -3.4e38f, m1 = -3.4e38f;
    int coli = g_col_s[start];
    for (int i = start; i < end; i++) {
        int coln   = (i + 1 < end) ? g_col_s[i + 1] : 0;  // prefetch next col
        float adj  = g_adj_s[i];
        float4 kk  = k4p[coli * 32 + lane];
        float  ec  = eigs[coli * 32 + lane];
        float part = fmaf(q.x, kk.x, fmaf(q.y, kk.y, fmaf(q.z, kk.z, q.w * kk.w))) * inv
                   + lambda * (er * ec);
#pragma unroll
        for (int o = 16; o; o >>= 1)
            part += __shfl_xor_sync(0xffffffffu, part, o);
        if (!lane) g_s0[i] = part;   // all lanes hold the full sum after xor-reduce
        m0 = fmaxf(m0, part);
        m1 = fmaxf(m1, c * adj);
        coli = coln;
    }
    __syncwarp();  // make lane-0 g_s0 writes visible to all lanes

    // -------- pass 2: softmax partition functions (lane-parallel) --------
    float z0 = 0.f, z1 = 0.f;
    for (int j = start + lane; j < end; j += 32) {
        z0 += __expf(g_s0[j] - m0);
        z1 += __expf(c * g_adj_s[j] - m1);
    }
#pragma unroll
    for (int o = 16; o; o >>= 1) {
        z0 += __shfl_xor_sync(0xffffffffu, z0, o);
        z1 += __shfl_xor_sync(0xffffffffu, z1, o);
    }
    float i0 = 0.5f / z0;
    float i1 = 0.5f / z1;

    // -------- pass 3: out[r] = sum_e attn_e * v[col_e] --------
    float4 acc = make_float4(0.f, 0.f, 0.f, 0.f);
    int colj = g_col_s[start];
    for (int j = start; j < end; j++) {
        int coln = (j + 1 < end) ? g_col_s[j + 1] : 0;
        float w  = __expf(g_s0[j] - m0) * i0 + __expf(c * g_adj_s[j] - m1) * i1;
        float4 v = v4p[colj * 32 + lane];
        acc.x = fmaf(w, v.x, acc.x);
        acc.y = fmaf(w, v.y, acc.y);
        acc.z = fmaf(w, v.z, acc.z);
        acc.w = fmaf(w, v.w, acc.w);
        colj = coln;
    }
    out4[r * 32 + lane] = acc;
}

// ---------------------------------------------------------------------------
extern "C" void kernel_launch(void* const* d_in, const int* in_sizes, int n_in,
                              void* d_out, int out_size) {
    const float* q       = (const float*)d_in[0];
    const float* k       = (const float*)d_in[1];
    const float* v       = (const float*)d_in[2];
    const float* eigs    = (const float*)d_in[3];
    const float* adj     = (const float*)d_in[4];
    const float* lambda0 = (const float*)d_in[5];
    const float* gamma   = (const float*)d_in[6];
    const float* memb    = (const float*)d_in[7];
    const int*   row     = (const int*)d_in[8];
    const int*   col     = (const int*)d_in[9];
    const int*   mids    = (const int*)d_in[10];

    int n = in_sizes[10];  // N = len(motif_ids)
    int e = in_sizes[8];   // E = len(row)

    k_init<<<(n + 255) / 256, 256>>>(memb, mids, n);
    k_edge1<<<2048, 256>>>(row, col, e);
    k_scan<<<1, 1024>>>(lambda0, gamma, n, e);
    k_scatter<<<2048, 256>>>(row, col, adj, e);

    int warps = n;  // one warp per destination row
    k_main<<<(warps * 32 + 255) / 256, 256>>>(
        (const float4*)q, (const float4*)k, (const float4*)v, eigs,
        (float4*)d_out, n);
}